// round 1
// baseline (speedup 1.0000x reference)
#include <cuda_runtime.h>
#include <cuda_bf16.h>

// Problem constants
#define NN 1024
#define BB 8
#define EE 512
#define HH 8
#define DD 64

// Scratch (device globals: allocation-free per harness rules)
__device__ float g_Q[BB * HH * NN * DD];   // [bh][n][d]
__device__ float g_K[BB * HH * NN * DD];
__device__ float g_V[BB * HH * NN * DD];
__device__ float g_Att[NN * BB * EE];      // [n][b][e]

// ---------------------------------------------------------------------------
// GEMM: C[r][c] = sum_k A[r][k] * W[c][k] + bias[c]
//   M = 8192 (= N*B), Ncols = 512, K = 512. A row-major, W row-major (A @ W^T).
// MODE 0/1/2: write to g_Q/g_K/g_V in [bh][n][d] layout (A = nodes)
// MODE 3:     A = g_Att, write row-major to outp (final output)
// ---------------------------------------------------------------------------
template <int MODE>
__global__ __launch_bounds__(256) void gemm_bias(
    const float* __restrict__ Ain,
    const float* __restrict__ W,
    const float* __restrict__ bias,
    float* __restrict__ outp)
{
    __shared__ float As[16][64];
    __shared__ float Ws[16][64];

    const float* __restrict__ A = (MODE == 3) ? g_Att : Ain;

    const int tid = threadIdx.x;
    const int tx = tid & 15;
    const int ty = tid >> 4;
    const int r0 = blockIdx.x * 64;
    const int c0 = blockIdx.y * 64;

    const int lrow = tid >> 2;        // 0..63
    const int lk   = (tid & 3) << 2;  // 0,4,8,12

    float acc[4][4];
#pragma unroll
    for (int i = 0; i < 4; i++)
#pragma unroll
        for (int j = 0; j < 4; j++) acc[i][j] = 0.f;

    for (int kk = 0; kk < 512; kk += 16) {
        float4 av = *(const float4*)&A[(r0 + lrow) * 512 + kk + lk];
        float4 wv = *(const float4*)&W[(c0 + lrow) * 512 + kk + lk];
        As[lk + 0][lrow] = av.x; As[lk + 1][lrow] = av.y;
        As[lk + 2][lrow] = av.z; As[lk + 3][lrow] = av.w;
        Ws[lk + 0][lrow] = wv.x; Ws[lk + 1][lrow] = wv.y;
        Ws[lk + 2][lrow] = wv.z; Ws[lk + 3][lrow] = wv.w;
        __syncthreads();

#pragma unroll
        for (int k = 0; k < 16; k++) {
            float4 a = *(const float4*)&As[k][ty << 2];
            float4 b = *(const float4*)&Ws[k][tx << 2];
            acc[0][0] += a.x * b.x; acc[0][1] += a.x * b.y;
            acc[0][2] += a.x * b.z; acc[0][3] += a.x * b.w;
            acc[1][0] += a.y * b.x; acc[1][1] += a.y * b.y;
            acc[1][2] += a.y * b.z; acc[1][3] += a.y * b.w;
            acc[2][0] += a.z * b.x; acc[2][1] += a.z * b.y;
            acc[2][2] += a.z * b.z; acc[2][3] += a.z * b.w;
            acc[3][0] += a.w * b.x; acc[3][1] += a.w * b.y;
            acc[3][2] += a.w * b.z; acc[3][3] += a.w * b.w;
        }
        __syncthreads();
    }

    float4 bv = *(const float4*)&bias[c0 + (tx << 2)];
#pragma unroll
    for (int rr = 0; rr < 4; rr++) {
        const int r = r0 + (ty << 2) + rr;
        float4 v = make_float4(acc[rr][0] + bv.x, acc[rr][1] + bv.y,
                               acc[rr][2] + bv.z, acc[rr][3] + bv.w);
        const int c = c0 + (tx << 2);
        if (MODE <= 2) {
            float* qkv = (MODE == 0) ? g_Q : (MODE == 1) ? g_K : g_V;
            const int i = r >> 3;        // r / B
            const int b = r & 7;         // r % B
            const int h = c >> 6;        // c / D
            const int d = c & 63;        // c % D
            *(float4*)&qkv[(((size_t)(b * HH + h) * NN) + i) * DD + d] = v;
        } else {
            *(float4*)&outp[(size_t)r * 512 + c] = v;
        }
    }
}

// ---------------------------------------------------------------------------
// Flash-style attention. One block = 64 query rows for one (b,h).
// Each thread owns one query row: q[64] and o[64] live in registers, so the
// online-softmax max/sum are purely thread-local.
// Smem: K/V tile (16KB) + edges tile (16.6KB padded, reused as P buffer).
// ---------------------------------------------------------------------------
__global__ __launch_bounds__(64) void attn_kernel(
    const float* __restrict__ edges,
    const float* __restrict__ rel_bias)
{
    __shared__ float4 KVs[64 * 16];     // K or V tile: [j][d4]
    __shared__ float  Es[64][65];       // edges tile, then reused as P

    const int bh = blockIdx.y;
    const int b  = bh / HH;
    const int h  = bh % HH;
    const int i0 = blockIdx.x * 64;
    const int t  = threadIdx.x;         // query row within tile

    const float rb = rel_bias[h];
    const float NEG = -3.0e38f;

    // Load this thread's query row, pre-scaled by 1/sqrt(D)
    const float4* Qrow = (const float4*)&g_Q[(((size_t)bh * NN) + i0 + t) * DD];
    float4 q[16];
#pragma unroll
    for (int u = 0; u < 16; u++) {
        float4 qv = Qrow[u];
        q[u] = make_float4(qv.x * 0.125f, qv.y * 0.125f, qv.z * 0.125f, qv.w * 0.125f);
    }

    float4 o[16];
#pragma unroll
    for (int u = 0; u < 16; u++) o[u] = make_float4(0.f, 0.f, 0.f, 0.f);
    float m = NEG, l = 0.f;

    const float4* Kg4 = (const float4*)&g_K[(size_t)bh * NN * DD];
    const float4* Vg4 = (const float4*)&g_V[(size_t)bh * NN * DD];

    for (int jt = 0; jt < 16; jt++) {
        const int j0 = jt * 64;

        // Load K tile (coalesced: 16 lanes x consecutive float4)
#pragma unroll
        for (int u = 0; u < 16; u++) {
            const int j  = u * 4 + (t >> 4);
            const int d4 = t & 15;
            KVs[j * 16 + d4] = Kg4[(size_t)(j0 + j) * 16 + d4];
        }
        // Load edges tile (coalesced in j)
#pragma unroll
        for (int u = 0; u < 16; u++) {
            const int i  = u * 4 + (t >> 4);
            const int j4 = (t & 15) << 2;
            float4 ev = *(const float4*)&edges[(size_t)(i0 + i) * NN + j0 + j4];
            Es[i][j4 + 0] = ev.x; Es[i][j4 + 1] = ev.y;
            Es[i][j4 + 2] = ev.z; Es[i][j4 + 3] = ev.w;
        }
        __syncthreads();

        // S = q . k  (+ edge bias); write back into Es (reused as P buffer)
        float tmax = NEG;
        for (int j = 0; j < 64; j++) {
            float a0 = 0.f, a1 = 0.f, a2 = 0.f, a3 = 0.f;
#pragma unroll
            for (int d4 = 0; d4 < 16; d4++) {
                float4 kv = KVs[j * 16 + d4];
                a0 += q[d4].x * kv.x;
                a1 += q[d4].y * kv.y;
                a2 += q[d4].z * kv.z;
                a3 += q[d4].w * kv.w;
            }
            float s = ((a0 + a1) + (a2 + a3)) + Es[t][j] * rb;
            Es[t][j] = s;
            tmax = fmaxf(tmax, s);
        }
        __syncthreads();

        // Load V tile over K tile
#pragma unroll
        for (int u = 0; u < 16; u++) {
            const int j  = u * 4 + (t >> 4);
            const int d4 = t & 15;
            KVs[j * 16 + d4] = Vg4[(size_t)(j0 + j) * 16 + d4];
        }
        __syncthreads();

        // Online softmax rescale + PV accumulate
        const float mnew = fmaxf(m, tmax);
        const float corr = __expf(m - mnew);
        l *= corr;
#pragma unroll
        for (int u = 0; u < 16; u++) {
            o[u].x *= corr; o[u].y *= corr; o[u].z *= corr; o[u].w *= corr;
        }
        for (int j = 0; j < 64; j++) {
            const float p = __expf(Es[t][j] - mnew);
            l += p;
#pragma unroll
            for (int d4 = 0; d4 < 16; d4++) {
                float4 vv = KVs[j * 16 + d4];
                o[d4].x += p * vv.x;
                o[d4].y += p * vv.y;
                o[d4].z += p * vv.z;
                o[d4].w += p * vv.w;
            }
        }
        m = mnew;
        __syncthreads();   // protect KVs/Es before next tile's loads
    }

    const float inv = 1.f / l;
    float* Out = &g_Att[(((size_t)(i0 + t) * BB) + b) * EE + h * DD];
#pragma unroll
    for (int u = 0; u < 16; u++) {
        float4 v = make_float4(o[u].x * inv, o[u].y * inv, o[u].z * inv, o[u].w * inv);
        *(float4*)&Out[u * 4] = v;
    }
}

// ---------------------------------------------------------------------------
extern "C" void kernel_launch(void* const* d_in, const int* in_sizes, int n_in,
                              void* d_out, int out_size)
{
    const float* nodes = (const float*)d_in[0];
    const float* edges = (const float*)d_in[1];
    const float* Wq    = (const float*)d_in[2];
    const float* bq    = (const float*)d_in[3];
    const float* Wk    = (const float*)d_in[4];
    const float* bk    = (const float*)d_in[5];
    const float* Wv    = (const float*)d_in[6];
    const float* bv    = (const float*)d_in[7];
    const float* rel   = (const float*)d_in[8];
    const float* Wo    = (const float*)d_in[9];
    const float* bo    = (const float*)d_in[10];
    float* out = (float*)d_out;

    dim3 gproj(8192 / 64, 512 / 64);   // (128, 8)
    gemm_bias<0><<<gproj, 256>>>(nodes, Wq, bq, nullptr);
    gemm_bias<1><<<gproj, 256>>>(nodes, Wk, bk, nullptr);
    gemm_bias<2><<<gproj, 256>>>(nodes, Wv, bv, nullptr);

    attn_kernel<<<dim3(NN / 64, BB * HH), 64>>>(edges, rel);

    gemm_bias<3><<<gproj, 256>>>(nullptr, Wo, bo, out);
}

// round 3
// speedup vs baseline: 3.6474x; 3.6474x over previous
#include <cuda_runtime.h>
#include <cstdint>

#define NN 1024
#define BB 8
#define EE 512
#define HH 8
#define DD 64
#define L2E 1.4426950408889634f

// Scratch (device globals: allocation-free per harness rules)
__device__ float g_Q[BB * HH * NN * DD];   // [bh][n][d]
__device__ float g_K[BB * HH * NN * DD];   // [bh][n][d]
__device__ float g_V[BB * HH * NN * DD];   // [bh][n][d]
__device__ float g_Att[NN * BB * EE];      // [n][b][e]

// ---------------------------------------------------------------------------
// helpers
// ---------------------------------------------------------------------------
__device__ __forceinline__ uint32_t f2tf(float f) {
    uint32_t r;
    asm("cvt.rna.tf32.f32 %0, %1;" : "=r"(r) : "f"(f));
    return r;
}
__device__ __forceinline__ float ex2f(float x) {
    float r;
    asm("ex2.approx.f32 %0, %1;" : "=f"(r) : "f"(x));
    return r;
}
// D(16x8,f32) += A(16x8,tf32 row) * B(8x8,tf32 col)
__device__ __forceinline__ void mma8(float* d, const uint32_t* a,
                                     uint32_t b0, uint32_t b1) {
    asm volatile(
        "mma.sync.aligned.m16n8k8.row.col.f32.tf32.tf32.f32 "
        "{%0,%1,%2,%3}, {%4,%5,%6,%7}, {%8,%9}, {%0,%1,%2,%3};"
        : "+f"(d[0]), "+f"(d[1]), "+f"(d[2]), "+f"(d[3])
        : "r"(a[0]), "r"(a[1]), "r"(a[2]), "r"(a[3]), "r"(b0), "r"(b1));
}

// ===========================================================================
// Attention: block = 64 q-rows x one (b,h); 128 threads (4 warps).
// Warp w owns q-rows [16w,16w+16). Q frags in regs; O accumulates in regs.
// Smem: Ks[64][68] (reused as P after MMA1), Vs[64][68], tf32 bits.
// ===========================================================================
__global__ void __launch_bounds__(128) attn_mma(
    const float* __restrict__ edges, const float* __restrict__ rel)
{
    __shared__ uint32_t Ks[64 * 68];
    __shared__ uint32_t Vs[64 * 68];

    const int tid  = threadIdx.x;
    const int w    = tid >> 5;
    const int lane = tid & 31;
    const int g    = lane >> 2;     // 0..7
    const int c    = lane & 3;      // 0..3
    const int bh   = blockIdx.y, b = bh >> 3, h = bh & 7;
    const int i0   = blockIdx.x * 64;
    const float rbl2e = rel[h] * L2E;

    // ---- Q fragments (pre-scaled by log2e/8) ----
    const float* Qb = g_Q + ((size_t)bh * NN + i0 + 16 * w) * DD;
    uint32_t qa[8][4];
#pragma unroll
    for (int kt = 0; kt < 8; kt++) {
        const float s = L2E * 0.125f;
        qa[kt][0] = f2tf(Qb[g * 64 + 8 * kt + c] * s);
        qa[kt][1] = f2tf(Qb[(g + 8) * 64 + 8 * kt + c] * s);
        qa[kt][2] = f2tf(Qb[g * 64 + 8 * kt + c + 4] * s);
        qa[kt][3] = f2tf(Qb[(g + 8) * 64 + 8 * kt + c + 4] * s);
    }

    float oacc[8][4];
#pragma unroll
    for (int nt = 0; nt < 8; nt++)
#pragma unroll
        for (int e = 0; e < 4; e++) oacc[nt][e] = 0.f;
    float lsum0 = 0.f, lsum1 = 0.f;

    const float4* Kg = (const float4*)(g_K + (size_t)bh * NN * DD);
    const float4* Vg = (const float4*)(g_V + (size_t)bh * NN * DD);

    for (int jt = 0; jt < 16; jt++) {
        const int j0 = jt * 64;
        __syncthreads();   // prior tile's MMA2 reads done before restage

        // ---- stage K and V tiles (tf32) ----
#pragma unroll
        for (int u = 0; u < 8; u++) {
            const int idx = u * 128 + tid;        // 0..1023
            const int row = idx >> 4, q4 = idx & 15;
            float4 kv = Kg[(size_t)(j0 + row) * 16 + q4];
            uint32_t* p = &Ks[row * 68 + q4 * 4];
            p[0] = f2tf(kv.x); p[1] = f2tf(kv.y);
            p[2] = f2tf(kv.z); p[3] = f2tf(kv.w);
            float4 vv = Vg[(size_t)(j0 + row) * 16 + q4];
            uint32_t* q = &Vs[row * 68 + q4 * 4];
            q[0] = f2tf(vv.x); q[1] = f2tf(vv.y);
            q[2] = f2tf(vv.z); q[3] = f2tf(vv.w);
        }
        __syncthreads();

        // ---- MMA1: S = Q K^T   (S in log2e units) ----
        float sacc[8][4];
#pragma unroll
        for (int nt = 0; nt < 8; nt++)
#pragma unroll
            for (int e = 0; e < 4; e++) sacc[nt][e] = 0.f;
#pragma unroll
        for (int kt = 0; kt < 8; kt++) {
#pragma unroll
            for (int nt = 0; nt < 8; nt++) {
                uint32_t b0 = Ks[(8 * nt + g) * 68 + 8 * kt + c];
                uint32_t b1 = Ks[(8 * nt + g) * 68 + 8 * kt + c + 4];
                mma8(sacc[nt], qa[kt], b0, b1);
            }
        }
        __syncthreads();   // all warps' MMA1 done -> Ks reusable as P

        // ---- epilogue: p = 2^(s + e*rb*log2e); P -> Ks strip (tf32) ----
        uint32_t* Ps = &Ks[w * 16 * 68];
        const float* E0 = edges + (size_t)(i0 + 16 * w + g) * NN + j0;
        const float* E1 = E0 + 8 * NN;
#pragma unroll
        for (int nt = 0; nt < 8; nt++) {
            float2 e0 = *(const float2*)(E0 + 8 * nt + 2 * c);
            float2 e1 = *(const float2*)(E1 + 8 * nt + 2 * c);
            float p00 = ex2f(fmaf(e0.x, rbl2e, sacc[nt][0]));
            float p01 = ex2f(fmaf(e0.y, rbl2e, sacc[nt][1]));
            float p10 = ex2f(fmaf(e1.x, rbl2e, sacc[nt][2]));
            float p11 = ex2f(fmaf(e1.y, rbl2e, sacc[nt][3]));
            lsum0 += p00 + p01;
            lsum1 += p10 + p11;
            uint2 t0 = make_uint2(f2tf(p00), f2tf(p01));
            uint2 t1 = make_uint2(f2tf(p10), f2tf(p11));
            *(uint2*)&Ps[g * 68 + 8 * nt + 2 * c] = t0;
            *(uint2*)&Ps[(g + 8) * 68 + 8 * nt + 2 * c] = t1;
        }
        __syncwarp();

        // ---- MMA2: O += P V  (A = own P strip, B = Vs[j][d]) ----
#pragma unroll
        for (int kt = 0; kt < 8; kt++) {
            uint32_t a[4];
            a[0] = Ps[g * 68 + 8 * kt + c];
            a[1] = Ps[(g + 8) * 68 + 8 * kt + c];
            a[2] = Ps[g * 68 + 8 * kt + c + 4];
            a[3] = Ps[(g + 8) * 68 + 8 * kt + c + 4];
#pragma unroll
            for (int nt = 0; nt < 8; nt++) {
                uint32_t b0 = Vs[(8 * kt + c) * 68 + 8 * nt + g];
                uint32_t b1 = Vs[(8 * kt + c + 4) * 68 + 8 * nt + g];
                mma8(oacc[nt], a, b0, b1);
            }
        }
    }

    // ---- finalize: row sums across quad, normalize, store ----
    lsum0 += __shfl_xor_sync(0xFFFFFFFF, lsum0, 1);
    lsum0 += __shfl_xor_sync(0xFFFFFFFF, lsum0, 2);
    lsum1 += __shfl_xor_sync(0xFFFFFFFF, lsum1, 1);
    lsum1 += __shfl_xor_sync(0xFFFFFFFF, lsum1, 2);
    const float inv0 = 1.0f / lsum0;
    const float inv1 = 1.0f / lsum1;

    float* O0 = g_Att + ((size_t)(i0 + 16 * w + g) * BB + b) * EE + h * DD;
    float* O1 = O0 + (size_t)8 * BB * EE;
#pragma unroll
    for (int nt = 0; nt < 8; nt++) {
        *(float2*)(O0 + 8 * nt + 2 * c) =
            make_float2(oacc[nt][0] * inv0, oacc[nt][1] * inv0);
        *(float2*)(O1 + 8 * nt + 2 * c) =
            make_float2(oacc[nt][2] * inv1, oacc[nt][3] * inv1);
    }
}

// ===========================================================================
// GEMM (tf32 mma.sync): C[r][c] = sum_k A[r][k]*W[c][k] + bias[c]
// M=8192, N=512, K=512. Block 128x64, K-chunk 32, 256 thr (8 warps, 4x2).
// MODE 0/1/2 -> g_Q/g_K/g_V in [bh][n][d]; MODE 3 -> out row-major.
// ===========================================================================
template <int MODE>
__global__ void __launch_bounds__(256) gemm_mma(
    const float* __restrict__ Ain, const float* __restrict__ W,
    const float* __restrict__ bias, float* __restrict__ outp)
{
    __shared__ uint32_t As[128 * 36];
    __shared__ uint32_t Ws[64 * 36];

    const float* __restrict__ A = (MODE == 3) ? g_Att : Ain;
    const int tid  = threadIdx.x;
    const int w    = tid >> 5;
    const int lane = tid & 31;
    const int g    = lane >> 2, c = lane & 3;
    const int wm   = w & 3, wn = w >> 2;
    const int r0   = blockIdx.x * 128, c0 = blockIdx.y * 64;

    float acc[2][4][4];
#pragma unroll
    for (int mt = 0; mt < 2; mt++)
#pragma unroll
        for (int nt = 0; nt < 4; nt++)
#pragma unroll
            for (int e = 0; e < 4; e++) acc[mt][nt][e] = 0.f;

    for (int kk = 0; kk < 512; kk += 32) {
        __syncthreads();
        // stage A chunk 128x32
#pragma unroll
        for (int u = 0; u < 4; u++) {
            const int idx = u * 256 + tid;       // 0..1023
            const int row = idx >> 3, q4 = idx & 7;
            float4 av = *(const float4*)&A[(size_t)(r0 + row) * 512 + kk + q4 * 4];
            uint32_t* p = &As[row * 36 + q4 * 4];
            p[0] = f2tf(av.x); p[1] = f2tf(av.y);
            p[2] = f2tf(av.z); p[3] = f2tf(av.w);
        }
        // stage W chunk 64x32
#pragma unroll
        for (int u = 0; u < 2; u++) {
            const int idx = u * 256 + tid;       // 0..511
            const int row = idx >> 3, q4 = idx & 7;
            float4 wv = *(const float4*)&W[(size_t)(c0 + row) * 512 + kk + q4 * 4];
            uint32_t* p = &Ws[row * 36 + q4 * 4];
            p[0] = f2tf(wv.x); p[1] = f2tf(wv.y);
            p[2] = f2tf(wv.z); p[3] = f2tf(wv.w);
        }
        __syncthreads();

#pragma unroll
        for (int kt = 0; kt < 4; kt++) {
            uint32_t a[2][4];
#pragma unroll
            for (int mt = 0; mt < 2; mt++) {
                const int base = 32 * wm + 16 * mt;
                a[mt][0] = As[(base + g) * 36 + 8 * kt + c];
                a[mt][1] = As[(base + g + 8) * 36 + 8 * kt + c];
                a[mt][2] = As[(base + g) * 36 + 8 * kt + c + 4];
                a[mt][3] = As[(base + g + 8) * 36 + 8 * kt + c + 4];
            }
#pragma unroll
            for (int nt = 0; nt < 4; nt++) {
                uint32_t b0 = Ws[(32 * wn + 8 * nt + g) * 36 + 8 * kt + c];
                uint32_t b1 = Ws[(32 * wn + 8 * nt + g) * 36 + 8 * kt + c + 4];
                mma8(acc[0][nt], a[0], b0, b1);
                mma8(acc[1][nt], a[1], b0, b1);
            }
        }
    }

    // ---- epilogue: bias + scatter ----
#pragma unroll
    for (int nt = 0; nt < 4; nt++) {
        const int col = c0 + 32 * wn + 8 * nt + 2 * c;
        float2 bb = *(const float2*)&bias[col];
#pragma unroll
        for (int mt = 0; mt < 2; mt++) {
#pragma unroll
            for (int rh = 0; rh < 2; rh++) {
                const int row = r0 + 32 * wm + 16 * mt + g + 8 * rh;
                float2 v = make_float2(acc[mt][nt][2 * rh] + bb.x,
                                       acc[mt][nt][2 * rh + 1] + bb.y);
                if (MODE <= 2) {
                    float* dst = (MODE == 0) ? g_Q : (MODE == 1) ? g_K : g_V;
                    const int i = row >> 3, bq = row & 7;
                    const int hh = col >> 6, d = col & 63;
                    *(float2*)&dst[(((size_t)(bq * HH + hh)) * NN + i) * DD + d] = v;
                } else {
                    *(float2*)&outp[(size_t)row * 512 + col] = v;
                }
            }
        }
    }
}

// ===========================================================================
extern "C" void kernel_launch(void* const* d_in, const int* in_sizes, int n_in,
                              void* d_out, int out_size)
{
    const float* nodes = (const float*)d_in[0];
    const float* edges = (const float*)d_in[1];
    const float* Wq    = (const float*)d_in[2];
    const float* bq    = (const float*)d_in[3];
    const float* Wk    = (const float*)d_in[4];
    const float* bk    = (const float*)d_in[5];
    const float* Wv    = (const float*)d_in[6];
    const float* bv    = (const float*)d_in[7];
    const float* rel   = (const float*)d_in[8];
    const float* Wo    = (const float*)d_in[9];
    const float* bo    = (const float*)d_in[10];
    float* out = (float*)d_out;

    dim3 gproj(8192 / 128, 512 / 64);   // (64, 8)
    gemm_mma<0><<<gproj, 256>>>(nodes, Wq, bq, nullptr);
    gemm_mma<1><<<gproj, 256>>>(nodes, Wk, bk, nullptr);
    gemm_mma<2><<<gproj, 256>>>(nodes, Wv, bv, nullptr);

    attn_mma<<<dim3(NN / 64, BB * HH), 128>>>(edges, rel);

    gemm_mma<3><<<gproj, 256>>>(nullptr, Wo, bo, out);
}

// round 4
// speedup vs baseline: 4.4939x; 1.2321x over previous
#include <cuda_runtime.h>
#include <cstdint>

#define NN 1024
#define BB 8
#define EE 512
#define HH 8
#define DD 64
#define L2E 1.4426950408889634f

// Scratch (device globals: allocation-free per harness rules)
__device__ float g_Q[BB * HH * NN * DD];   // [bh][n][d]
__device__ float g_K[BB * HH * NN * DD];   // [bh][n][d]
__device__ float g_V[BB * HH * NN * DD];   // [bh][n][d]
__device__ float g_Att[NN * BB * EE];      // [n][b][e]

// ---------------------------------------------------------------------------
// helpers
// ---------------------------------------------------------------------------
__device__ __forceinline__ uint32_t f2tf(float f) {
    uint32_t r;
    asm("cvt.rna.tf32.f32 %0, %1;" : "=r"(r) : "f"(f));
    return r;
}
__device__ __forceinline__ float ex2f(float x) {
    float r;
    asm("ex2.approx.f32 %0, %1;" : "=f"(r) : "f"(x));
    return r;
}
__device__ __forceinline__ void mma8(float* d, const uint32_t* a,
                                     uint32_t b0, uint32_t b1) {
    asm volatile(
        "mma.sync.aligned.m16n8k8.row.col.f32.tf32.tf32.f32 "
        "{%0,%1,%2,%3}, {%4,%5,%6,%7}, {%8,%9}, {%0,%1,%2,%3};"
        : "+f"(d[0]), "+f"(d[1]), "+f"(d[2]), "+f"(d[3])
        : "r"(a[0]), "r"(a[1]), "r"(a[2]), "r"(a[3]), "r"(b0), "r"(b1));
}
__device__ __forceinline__ uint32_t smaddr(const void* p) {
    uint32_t a;
    asm("{ .reg .u64 t; cvta.to.shared.u64 t, %1; cvt.u32.u64 %0, t; }" : "=r"(a) : "l"(p));
    return a;
}
__device__ __forceinline__ void cpa16(uint32_t s, const void* g) {
    asm volatile("cp.async.ca.shared.global [%0], [%1], 16;" :: "r"(s), "l"(g) : "memory");
}
#define CPA_COMMIT() asm volatile("cp.async.commit_group;" ::: "memory")

// ===========================================================================
// Attention: block = 128 q-rows x one (b,h); 128 threads (4 warps).
// Warp w owns q-rows [32w, 32w+32) as 2 m16 fragments. Q, O in registers.
// Smem (dynamic): Ks[64][68], Vs[64][72], Ps[128][68]  (tf32 bits, padded).
//   stride 68 (=4 mod 32): conflict-free for (g*stride + c) reads  [K, P]
//   stride 72 (=8 mod 32): conflict-free for (c*stride + g) reads  [V]
// ===========================================================================
#define SK 68
#define SV 72
#define SP 68
#define A_OK 0
#define A_OV (64 * SK)            // 4352 words
#define A_OP (A_OV + 64 * SV)     // 8960 words
#define ATT_WORDS (A_OP + 128 * SP)   // 17664 words
#define ATT_BYTES (ATT_WORDS * 4)     // 70656 B

__global__ void __launch_bounds__(128) attn_mma(
    const float* __restrict__ edges, const float* __restrict__ rel)
{
    extern __shared__ uint32_t sm[];
    uint32_t* Ks = sm + A_OK;
    uint32_t* Vs = sm + A_OV;
    uint32_t* Ps = sm + A_OP;

    const int tid  = threadIdx.x;
    const int w    = tid >> 5;
    const int lane = tid & 31;
    const int g    = lane >> 2;     // 0..7
    const int c    = lane & 3;      // 0..3
    const int bh   = blockIdx.y, b = bh >> 3, h = bh & 7;
    const int i0   = blockIdx.x * 128;
    const float rbl2e = rel[h] * L2E;

    // ---- Q fragments (pre-scaled by log2e/8): rows 32w+16mf+{g,g+8} ----
    const float* Qb = g_Q + ((size_t)bh * NN + i0 + 32 * w) * DD;
    uint32_t qa[2][8][4];
#pragma unroll
    for (int mf = 0; mf < 2; mf++) {
        const float s = L2E * 0.125f;
        const float* Qm = Qb + 16 * mf * DD;
#pragma unroll
        for (int kt = 0; kt < 8; kt++) {
            qa[mf][kt][0] = f2tf(Qm[g * 64 + 8 * kt + c] * s);
            qa[mf][kt][1] = f2tf(Qm[(g + 8) * 64 + 8 * kt + c] * s);
            qa[mf][kt][2] = f2tf(Qm[g * 64 + 8 * kt + c + 4] * s);
            qa[mf][kt][3] = f2tf(Qm[(g + 8) * 64 + 8 * kt + c + 4] * s);
        }
    }

    float oacc[2][8][4];
#pragma unroll
    for (int mf = 0; mf < 2; mf++)
#pragma unroll
        for (int nt = 0; nt < 8; nt++)
#pragma unroll
            for (int e = 0; e < 4; e++) oacc[mf][nt][e] = 0.f;
    float l00 = 0.f, l01 = 0.f, l10 = 0.f, l11 = 0.f;

    const float4* Kg = (const float4*)(g_K + (size_t)bh * NN * DD);
    const float4* Vg = (const float4*)(g_V + (size_t)bh * NN * DD);

    for (int jt = 0; jt < 16; jt++) {
        const int j0 = jt * 64;
        __syncthreads();   // all warps done reading Ks/Vs of previous tile

        // ---- stage K [j][d] stride 68, V [j][d] stride 72 (tf32) ----
#pragma unroll
        for (int u = 0; u < 8; u++) {
            const int idx = u * 128 + tid;        // 0..1023
            const int row = idx >> 4, q4 = idx & 15;
            float4 kv = Kg[(size_t)(j0 + row) * 16 + q4];
            uint32_t* p = &Ks[row * SK + q4 * 4];
            p[0] = f2tf(kv.x); p[1] = f2tf(kv.y);
            p[2] = f2tf(kv.z); p[3] = f2tf(kv.w);
            float4 vv = Vg[(size_t)(j0 + row) * 16 + q4];
            uint32_t* q = &Vs[row * SV + q4 * 4];
            q[0] = f2tf(vv.x); q[1] = f2tf(vv.y);
            q[2] = f2tf(vv.z); q[3] = f2tf(vv.w);
        }
        __syncthreads();

        // ---- MMA1: S = Q K^T  (both m-frags share each B fragment) ----
        float sacc[2][8][4];
#pragma unroll
        for (int mf = 0; mf < 2; mf++)
#pragma unroll
            for (int nt = 0; nt < 8; nt++)
#pragma unroll
                for (int e = 0; e < 4; e++) sacc[mf][nt][e] = 0.f;
#pragma unroll
        for (int kt = 0; kt < 8; kt++) {
#pragma unroll
            for (int nt = 0; nt < 8; nt++) {
                uint32_t b0 = Ks[(8 * nt + g) * SK + 8 * kt + c];
                uint32_t b1 = Ks[(8 * nt + g) * SK + 8 * kt + c + 4];
                mma8(sacc[0][nt], qa[0][kt], b0, b1);
                mma8(sacc[1][nt], qa[1][kt], b0, b1);
            }
        }

        // ---- epilogue: p = 2^(s + e*rb*log2e); P -> own rows of Ps ----
#pragma unroll
        for (int mf = 0; mf < 2; mf++) {
            const int rowb = 32 * w + 16 * mf;
            const float* E0 = edges + (size_t)(i0 + rowb + g) * NN + j0;
            const float* E1 = E0 + 8 * NN;
            float ls0 = 0.f, ls1 = 0.f;
#pragma unroll
            for (int nt = 0; nt < 8; nt++) {
                float2 e0 = *(const float2*)(E0 + 8 * nt + 2 * c);
                float2 e1 = *(const float2*)(E1 + 8 * nt + 2 * c);
                float p00 = ex2f(fmaf(e0.x, rbl2e, sacc[mf][nt][0]));
                float p01 = ex2f(fmaf(e0.y, rbl2e, sacc[mf][nt][1]));
                float p10 = ex2f(fmaf(e1.x, rbl2e, sacc[mf][nt][2]));
                float p11 = ex2f(fmaf(e1.y, rbl2e, sacc[mf][nt][3]));
                ls0 += p00 + p01;
                ls1 += p10 + p11;
                *(uint2*)&Ps[(rowb + g) * SP + 8 * nt + 2 * c] =
                    make_uint2(f2tf(p00), f2tf(p01));
                *(uint2*)&Ps[(rowb + g + 8) * SP + 8 * nt + 2 * c] =
                    make_uint2(f2tf(p10), f2tf(p11));
            }
            if (mf == 0) { l00 += ls0; l01 += ls1; }
            else         { l10 += ls0; l11 += ls1; }
        }
        __syncwarp();

        // ---- MMA2: O += P V  (A = own P rows, B = Vs) ----
#pragma unroll
        for (int kt = 0; kt < 8; kt++) {
            uint32_t a[2][4];
#pragma unroll
            for (int mf = 0; mf < 2; mf++) {
                const int rowb = 32 * w + 16 * mf;
                a[mf][0] = Ps[(rowb + g) * SP + 8 * kt + c];
                a[mf][1] = Ps[(rowb + g + 8) * SP + 8 * kt + c];
                a[mf][2] = Ps[(rowb + g) * SP + 8 * kt + c + 4];
                a[mf][3] = Ps[(rowb + g + 8) * SP + 8 * kt + c + 4];
            }
#pragma unroll
            for (int nt = 0; nt < 8; nt++) {
                uint32_t b0 = Vs[(8 * kt + c) * SV + 8 * nt + g];
                uint32_t b1 = Vs[(8 * kt + c + 4) * SV + 8 * nt + g];
                mma8(oacc[0][nt], a[0], b0, b1);
                mma8(oacc[1][nt], a[1], b0, b1);
            }
        }
    }

    // ---- finalize: quad-reduce row sums, normalize, store ----
    l00 += __shfl_xor_sync(0xFFFFFFFF, l00, 1);
    l00 += __shfl_xor_sync(0xFFFFFFFF, l00, 2);
    l01 += __shfl_xor_sync(0xFFFFFFFF, l01, 1);
    l01 += __shfl_xor_sync(0xFFFFFFFF, l01, 2);
    l10 += __shfl_xor_sync(0xFFFFFFFF, l10, 1);
    l10 += __shfl_xor_sync(0xFFFFFFFF, l10, 2);
    l11 += __shfl_xor_sync(0xFFFFFFFF, l11, 1);
    l11 += __shfl_xor_sync(0xFFFFFFFF, l11, 2);
    const float inv[2][2] = {{1.0f / l00, 1.0f / l01}, {1.0f / l10, 1.0f / l11}};

#pragma unroll
    for (int mf = 0; mf < 2; mf++) {
        const int rowb = i0 + 32 * w + 16 * mf;
        float* O0 = g_Att + ((size_t)(rowb + g) * BB + b) * EE + h * DD;
        float* O1 = O0 + (size_t)8 * BB * EE;
#pragma unroll
        for (int nt = 0; nt < 8; nt++) {
            *(float2*)(O0 + 8 * nt + 2 * c) =
                make_float2(oacc[mf][nt][0] * inv[mf][0], oacc[mf][nt][1] * inv[mf][0]);
            *(float2*)(O1 + 8 * nt + 2 * c) =
                make_float2(oacc[mf][nt][2] * inv[mf][1], oacc[mf][nt][3] * inv[mf][1]);
        }
    }
}

// ===========================================================================
// GEMM (tf32 mma.sync + cp.async double buffer):
//   C[r][c] = sum_k A[r][k]*W[c][k] + bias[c];  M=8192, K=512.
// Block 128x128, 256 thr (8 warps as 4m x 2n; warp tile 32x64), chunk 32.
// MODE 0: fused QKV (blockIdx.y selects Wq/Wk/Wv), scatter to g_Q/K/V.
// MODE 1: out-projection from g_Att, row-major out.
// Smem staged as raw fp32; cvt.rna.tf32 applied at fragment load.
// ===========================================================================
#define GST 36                       // row stride (words), =4 mod 32
#define GBUF (128 * GST)             // 4608 words per matrix per stage
#define GEMM_BYTES (4 * GBUF * 4)    // 2 stages x (A+W) = 73728 B

template <int MODE>
__global__ void __launch_bounds__(256) gemm_mma(
    const float* __restrict__ Ain,
    const float* __restrict__ W0, const float* __restrict__ W1,
    const float* __restrict__ W2,
    const float* __restrict__ bi0, const float* __restrict__ bi1,
    const float* __restrict__ bi2,
    float* __restrict__ outp)
{
    extern __shared__ uint32_t sg[];
    uint32_t* Ab = sg;               // [2][GBUF]
    uint32_t* Wb = sg + 2 * GBUF;

    const float* __restrict__ A = (MODE == 1) ? g_Att : Ain;
    const int which = (MODE == 0) ? (blockIdx.y >> 2) : 0;
    const float* __restrict__ W =
        (MODE == 0) ? (which == 0 ? W0 : which == 1 ? W1 : W2) : W0;
    const float* __restrict__ bias =
        (MODE == 0) ? (which == 0 ? bi0 : which == 1 ? bi1 : bi2) : bi0;
    const int c0 = (MODE == 0) ? ((blockIdx.y & 3) * 128) : (blockIdx.y * 128);
    const int r0 = blockIdx.x * 128;

    const int tid  = threadIdx.x;
    const int w    = tid >> 5;
    const int lane = tid & 31;
    const int g    = lane >> 2, c = lane & 3;
    const int wm   = w & 3, wn = w >> 2;

    const int srow = tid >> 3;       // 0..31
    const int sq4  = tid & 7;        // 0..7

    // stage chunk kk (columns kk..kk+31) into buffer bufsel
    auto stage = [&](int kk, int bufsel) {
        const uint32_t abase = smaddr(Ab + bufsel * GBUF);
        const uint32_t wbase = smaddr(Wb + bufsel * GBUF);
#pragma unroll
        for (int u = 0; u < 4; u++) {
            const int row = u * 32 + srow;
            cpa16(abase + (row * GST + sq4 * 4) * 4,
                  &A[(size_t)(r0 + row) * 512 + kk + sq4 * 4]);
            cpa16(wbase + (row * GST + sq4 * 4) * 4,
                  &W[(size_t)(c0 + row) * 512 + kk + sq4 * 4]);
        }
        CPA_COMMIT();
    };

    float acc[2][8][4];
#pragma unroll
    for (int mf = 0; mf < 2; mf++)
#pragma unroll
        for (int nt = 0; nt < 8; nt++)
#pragma unroll
            for (int e = 0; e < 4; e++) acc[mf][nt][e] = 0.f;

    stage(0, 0);

    for (int kc = 0; kc < 16; kc++) {
        if (kc < 15) {
            stage((kc + 1) * 32, (kc + 1) & 1);
            asm volatile("cp.async.wait_group 1;" ::: "memory");
        } else {
            asm volatile("cp.async.wait_group 0;" ::: "memory");
        }
        __syncthreads();

        const uint32_t* As = Ab + (kc & 1) * GBUF;
        const uint32_t* Ws = Wb + (kc & 1) * GBUF;
#pragma unroll
        for (int kt = 0; kt < 4; kt++) {
            uint32_t a[2][4];
#pragma unroll
            for (int mf = 0; mf < 2; mf++) {
                const int rr = 32 * wm + 16 * mf;
                a[mf][0] = f2tf(__uint_as_float(As[(rr + g) * GST + 8 * kt + c]));
                a[mf][1] = f2tf(__uint_as_float(As[(rr + g + 8) * GST + 8 * kt + c]));
                a[mf][2] = f2tf(__uint_as_float(As[(rr + g) * GST + 8 * kt + c + 4]));
                a[mf][3] = f2tf(__uint_as_float(As[(rr + g + 8) * GST + 8 * kt + c + 4]));
            }
#pragma unroll
            for (int nt = 0; nt < 8; nt++) {
                uint32_t b0 = f2tf(__uint_as_float(Ws[(64 * wn + 8 * nt + g) * GST + 8 * kt + c]));
                uint32_t b1 = f2tf(__uint_as_float(Ws[(64 * wn + 8 * nt + g) * GST + 8 * kt + c + 4]));
                mma8(acc[0][nt], a[0], b0, b1);
                mma8(acc[1][nt], a[1], b0, b1);
            }
        }
        __syncthreads();
    }

    // ---- epilogue: bias + scatter ----
#pragma unroll
    for (int nt = 0; nt < 8; nt++) {
        const int col = c0 + 64 * wn + 8 * nt + 2 * c;
        float2 bb = *(const float2*)&bias[col & 511];
#pragma unroll
        for (int mf = 0; mf < 2; mf++) {
#pragma unroll
            for (int rh = 0; rh < 2; rh++) {
                const int row = r0 + 32 * wm + 16 * mf + g + 8 * rh;
                float2 v = make_float2(acc[mf][nt][2 * rh] + bb.x,
                                       acc[mf][nt][2 * rh + 1] + bb.y);
                if (MODE == 0) {
                    float* dst = (which == 0) ? g_Q : (which == 1) ? g_K : g_V;
                    const int i = row >> 3, bq = row & 7;
                    const int cl = col & 511;
                    const int hh = cl >> 6, d = cl & 63;
                    *(float2*)&dst[(((size_t)(bq * HH + hh)) * NN + i) * DD + d] = v;
                } else {
                    *(float2*)&outp[(size_t)row * 512 + col] = v;
                }
            }
        }
    }
}

// ===========================================================================
extern "C" void kernel_launch(void* const* d_in, const int* in_sizes, int n_in,
                              void* d_out, int out_size)
{
    const float* nodes = (const float*)d_in[0];
    const float* edges = (const float*)d_in[1];
    const float* Wq    = (const float*)d_in[2];
    const float* bq    = (const float*)d_in[3];
    const float* Wk    = (const float*)d_in[4];
    const float* bk    = (const float*)d_in[5];
    const float* Wv    = (const float*)d_in[6];
    const float* bv    = (const float*)d_in[7];
    const float* rel   = (const float*)d_in[8];
    const float* Wo    = (const float*)d_in[9];
    const float* bo    = (const float*)d_in[10];
    float* out = (float*)d_out;

    static int inited = 0;
    if (!inited) {
        cudaFuncSetAttribute(attn_mma, cudaFuncAttributeMaxDynamicSharedMemorySize, ATT_BYTES);
        cudaFuncSetAttribute(gemm_mma<0>, cudaFuncAttributeMaxDynamicSharedMemorySize, GEMM_BYTES);
        cudaFuncSetAttribute(gemm_mma<1>, cudaFuncAttributeMaxDynamicSharedMemorySize, GEMM_BYTES);
        inited = 1;
    }

    // Fused QKV projection: cols [0,512)=Q, [512,1024)=K, [1024,1536)=V
    gemm_mma<0><<<dim3(64, 12), 256, GEMM_BYTES>>>(
        nodes, Wq, Wk, Wv, bq, bk, bv, nullptr);

    attn_mma<<<dim3(NN / 128, BB * HH), 128, ATT_BYTES>>>(edges, rel);

    gemm_mma<1><<<dim3(64, 4), 256, GEMM_BYTES>>>(
        nullptr, Wo, Wo, Wo, bo, bo, bo, out);
}

// round 5
// speedup vs baseline: 4.7074x; 1.0475x over previous
#include <cuda_runtime.h>
#include <cstdint>

#define NN 1024
#define BB 8
#define EE 512
#define HH 8
#define DD 64
#define L2E 1.4426950408889634f
#define QS (L2E * 0.125f)

// Scratch (device globals: allocation-free per harness rules)
// Q: tf32 bits, pre-scaled by L2E/8, layout [bh][n][d]
__device__ uint32_t g_Qu[BB * HH * NN * DD];
// K packed for MMA1 B-frags: [bh][j/8][d/8][lane=(j%8)*4+(d%4)][comp=(d%8)/4]
__device__ uint32_t g_Kpk[BB * HH * 65536];
// V packed for MMA2 B-frags: [bh][j/8][d/8][lane=(d%8)*4+(j%4)][comp=(j%8)/4]
__device__ uint32_t g_Vpk[BB * HH * 65536];
__device__ float    g_Att[NN * BB * EE];     // [n][b][e] fp32

// ---------------------------------------------------------------------------
// helpers
// ---------------------------------------------------------------------------
__device__ __forceinline__ uint32_t f2tf(float f) {
    uint32_t r;
    asm("cvt.rna.tf32.f32 %0, %1;" : "=r"(r) : "f"(f));
    return r;
}
__device__ __forceinline__ float ex2f(float x) {
    float r;
    asm("ex2.approx.f32 %0, %1;" : "=f"(r) : "f"(x));
    return r;
}
__device__ __forceinline__ void mma8(float* d, const uint32_t* a,
                                     uint32_t b0, uint32_t b1) {
    asm volatile(
        "mma.sync.aligned.m16n8k8.row.col.f32.tf32.tf32.f32 "
        "{%0,%1,%2,%3}, {%4,%5,%6,%7}, {%8,%9}, {%0,%1,%2,%3};"
        : "+f"(d[0]), "+f"(d[1]), "+f"(d[2]), "+f"(d[3])
        : "r"(a[0]), "r"(a[1]), "r"(a[2]), "r"(a[3]), "r"(b0), "r"(b1));
}
__device__ __forceinline__ uint32_t smaddr(const void* p) {
    uint32_t a;
    asm("{ .reg .u64 t; cvta.to.shared.u64 t, %1; cvt.u32.u64 %0, t; }" : "=r"(a) : "l"(p));
    return a;
}
__device__ __forceinline__ void cpa16(uint32_t s, const void* g) {
    asm volatile("cp.async.ca.shared.global [%0], [%1], 16;" :: "r"(s), "l"(g) : "memory");
}
#define CPA_COMMIT() asm volatile("cp.async.commit_group;" ::: "memory")
#define CPA_WAIT0()  asm volatile("cp.async.wait_group 0;" ::: "memory")
#define CPA_WAIT1()  asm volatile("cp.async.wait_group 1;" ::: "memory")

// ===========================================================================
// Attention: block = 128 q-rows x one (b,h); 128 threads (4 warps, 2 m-frags).
// K/V staged via cp.async from packed tf32 gmem, double-buffered.
// Smem: [2 stages][K 4096w | V 4096w] + P[128][68]  = 100352 B dynamic.
// ===========================================================================
#define SP 68
#define ATT_P_OFF 16384
#define ATT_WORDS (16384 + 128 * SP)
#define ATT_BYTES (ATT_WORDS * 4)    // 100352

__global__ void __launch_bounds__(128) attn_mma(
    const float* __restrict__ edges, const float* __restrict__ rel)
{
    extern __shared__ uint32_t sm[];
    uint32_t* Ps = sm + ATT_P_OFF;

    const int tid  = threadIdx.x;
    const int w    = tid >> 5;
    const int lane = tid & 31;
    const int g    = lane >> 2;     // 0..7
    const int c    = lane & 3;      // 0..3
    const int bh   = blockIdx.y, b = bh >> 3, h = bh & 7;
    const int i0   = blockIdx.x * 128;
    const float rbl2e = rel[h] * L2E;

    // ---- Q fragments (already tf32 + prescaled in gmem) ----
    const uint32_t* Qb = g_Qu + ((size_t)bh * NN + i0 + 32 * w) * DD;
    uint32_t qa[2][8][4];
#pragma unroll
    for (int mf = 0; mf < 2; mf++) {
        const uint32_t* Qm = Qb + 16 * mf * DD;
#pragma unroll
        for (int kt = 0; kt < 8; kt++) {
            qa[mf][kt][0] = Qm[g * 64 + 8 * kt + c];
            qa[mf][kt][1] = Qm[(g + 8) * 64 + 8 * kt + c];
            qa[mf][kt][2] = Qm[g * 64 + 8 * kt + c + 4];
            qa[mf][kt][3] = Qm[(g + 8) * 64 + 8 * kt + c + 4];
        }
    }

    float oacc[2][8][4];
#pragma unroll
    for (int mf = 0; mf < 2; mf++)
#pragma unroll
        for (int nt = 0; nt < 8; nt++)
#pragma unroll
            for (int e = 0; e < 4; e++) oacc[mf][nt][e] = 0.f;
    float l00 = 0.f, l01 = 0.f, l10 = 0.f, l11 = 0.f;

    const uint32_t* Kg = g_Kpk + (size_t)bh * 65536;
    const uint32_t* Vg = g_Vpk + (size_t)bh * 65536;

    // stage 64-j tile jt into buffer s (K 16KB + V 16KB, linear copy)
    auto stageKV = [&](int jt, int s) {
        const uint32_t kb = smaddr(sm) + s * 32768;
        const uint32_t vb = kb + 16384;
        const uint32_t* Kt = Kg + jt * 4096;
        const uint32_t* Vt = Vg + jt * 4096;
#pragma unroll
        for (int u = 0; u < 8; u++) {
            const int ch = u * 128 + tid;            // 0..1023 chunks of 16B
            cpa16(kb + ch * 16, Kt + ch * 4);
            cpa16(vb + ch * 16, Vt + ch * 4);
        }
        CPA_COMMIT();
    };

    stageKV(0, 0);

    for (int jt = 0; jt < 16; jt++) {
        const int j0 = jt * 64;
        CPA_WAIT0();
        __syncthreads();   // staged data visible; prev iter readers done

        if (jt < 15) stageKV(jt + 1, (jt + 1) & 1);   // prefetch next tile

        const uint32_t* Ks = sm + (jt & 1) * 8192;
        const uint32_t* Vs = Ks + 4096;
        const int lw = (g * 4 + c) * 2;               // lane word offset

        // ---- MMA1: S = Q K^T ----
        float sacc[2][8][4];
#pragma unroll
        for (int mf = 0; mf < 2; mf++)
#pragma unroll
            for (int nt = 0; nt < 8; nt++)
#pragma unroll
                for (int e = 0; e < 4; e++) sacc[mf][nt][e] = 0.f;
#pragma unroll
        for (int kt = 0; kt < 8; kt++) {
#pragma unroll
            for (int nt = 0; nt < 8; nt++) {
                uint2 bb = *(const uint2*)&Ks[(nt * 8 + kt) * 64 + lw];
                mma8(sacc[0][nt], qa[0][kt], bb.x, bb.y);
                mma8(sacc[1][nt], qa[1][kt], bb.x, bb.y);
            }
        }

        // ---- epilogue: p = 2^(s + e*rb*log2e); P -> own rows of Ps ----
#pragma unroll
        for (int mf = 0; mf < 2; mf++) {
            const int rowb = 32 * w + 16 * mf;
            const float* E0 = edges + (size_t)(i0 + rowb + g) * NN + j0;
            const float* E1 = E0 + 8 * NN;
            float ls0 = 0.f, ls1 = 0.f;
#pragma unroll
            for (int nt = 0; nt < 8; nt++) {
                float2 e0 = *(const float2*)(E0 + 8 * nt + 2 * c);
                float2 e1 = *(const float2*)(E1 + 8 * nt + 2 * c);
                float p00 = ex2f(fmaf(e0.x, rbl2e, sacc[mf][nt][0]));
                float p01 = ex2f(fmaf(e0.y, rbl2e, sacc[mf][nt][1]));
                float p10 = ex2f(fmaf(e1.x, rbl2e, sacc[mf][nt][2]));
                float p11 = ex2f(fmaf(e1.y, rbl2e, sacc[mf][nt][3]));
                ls0 += p00 + p01;
                ls1 += p10 + p11;
                *(uint2*)&Ps[(rowb + g) * SP + 8 * nt + 2 * c] =
                    make_uint2(f2tf(p00), f2tf(p01));
                *(uint2*)&Ps[(rowb + g + 8) * SP + 8 * nt + 2 * c] =
                    make_uint2(f2tf(p10), f2tf(p11));
            }
            if (mf == 0) { l00 += ls0; l01 += ls1; }
            else         { l10 += ls0; l11 += ls1; }
        }
        __syncwarp();

        // ---- MMA2: O += P V ----
#pragma unroll
        for (int kt = 0; kt < 8; kt++) {
            uint32_t a[2][4];
#pragma unroll
            for (int mf = 0; mf < 2; mf++) {
                const int rowb = 32 * w + 16 * mf;
                a[mf][0] = Ps[(rowb + g) * SP + 8 * kt + c];
                a[mf][1] = Ps[(rowb + g + 8) * SP + 8 * kt + c];
                a[mf][2] = Ps[(rowb + g) * SP + 8 * kt + c + 4];
                a[mf][3] = Ps[(rowb + g + 8) * SP + 8 * kt + c + 4];
            }
#pragma unroll
            for (int nt = 0; nt < 8; nt++) {
                uint2 bb = *(const uint2*)&Vs[(kt * 8 + nt) * 64 + lw];
                mma8(oacc[0][nt], a[0], bb.x, bb.y);
                mma8(oacc[1][nt], a[1], bb.x, bb.y);
            }
        }
    }

    // ---- finalize: quad-reduce row sums, normalize, store ----
    l00 += __shfl_xor_sync(0xFFFFFFFF, l00, 1);
    l00 += __shfl_xor_sync(0xFFFFFFFF, l00, 2);
    l01 += __shfl_xor_sync(0xFFFFFFFF, l01, 1);
    l01 += __shfl_xor_sync(0xFFFFFFFF, l01, 2);
    l10 += __shfl_xor_sync(0xFFFFFFFF, l10, 1);
    l10 += __shfl_xor_sync(0xFFFFFFFF, l10, 2);
    l11 += __shfl_xor_sync(0xFFFFFFFF, l11, 1);
    l11 += __shfl_xor_sync(0xFFFFFFFF, l11, 2);
    const float inv[2][2] = {{1.0f / l00, 1.0f / l01}, {1.0f / l10, 1.0f / l11}};

#pragma unroll
    for (int mf = 0; mf < 2; mf++) {
        const int rowb = i0 + 32 * w + 16 * mf;
        float* O0 = g_Att + ((size_t)(rowb + g) * BB + b) * EE + h * DD;
        float* O1 = O0 + (size_t)8 * BB * EE;
#pragma unroll
        for (int nt = 0; nt < 8; nt++) {
            *(float2*)(O0 + 8 * nt + 2 * c) =
                make_float2(oacc[mf][nt][0] * inv[mf][0], oacc[mf][nt][1] * inv[mf][0]);
            *(float2*)(O1 + 8 * nt + 2 * c) =
                make_float2(oacc[mf][nt][2] * inv[mf][1], oacc[mf][nt][3] * inv[mf][1]);
        }
    }
}

// ===========================================================================
// GEMM (tf32 mma.sync + cp.async double buffer), block 128x128, 256 thr.
// MODE 0: fused QKV; epilogue -> g_Qu (prescaled tf32) / g_Kpk / g_Vpk.
// MODE 1: out-projection from g_Att (fp32), row-major fp32 out.
// ===========================================================================
#define GST 36
#define GBUF (128 * GST)
#define GEMM_BYTES (4 * GBUF * 4)

template <int MODE>
__global__ void __launch_bounds__(256) gemm_mma(
    const float* __restrict__ Ain,
    const float* __restrict__ W0, const float* __restrict__ W1,
    const float* __restrict__ W2,
    const float* __restrict__ bi0, const float* __restrict__ bi1,
    const float* __restrict__ bi2,
    float* __restrict__ outp)
{
    extern __shared__ uint32_t sg[];
    uint32_t* Ab = sg;
    uint32_t* Wb = sg + 2 * GBUF;

    const float* __restrict__ A = (MODE == 1) ? g_Att : Ain;
    const int which = (MODE == 0) ? (blockIdx.y >> 2) : 0;
    const float* __restrict__ W =
        (MODE == 0) ? (which == 0 ? W0 : which == 1 ? W1 : W2) : W0;
    const float* __restrict__ bias =
        (MODE == 0) ? (which == 0 ? bi0 : which == 1 ? bi1 : bi2) : bi0;
    const int c0 = (MODE == 0) ? ((blockIdx.y & 3) * 128) : (blockIdx.y * 128);
    const int r0 = blockIdx.x * 128;

    const int tid  = threadIdx.x;
    const int w    = tid >> 5;
    const int lane = tid & 31;
    const int g    = lane >> 2, c = lane & 3;
    const int wm   = w & 3, wn = w >> 2;
    const int srow = tid >> 3;
    const int sq4  = tid & 7;

    auto stage = [&](int kk, int bufsel) {
        const uint32_t abase = smaddr(Ab + bufsel * GBUF);
        const uint32_t wbase = smaddr(Wb + bufsel * GBUF);
#pragma unroll
        for (int u = 0; u < 4; u++) {
            const int row = u * 32 + srow;
            cpa16(abase + (row * GST + sq4 * 4) * 4,
                  &A[(size_t)(r0 + row) * 512 + kk + sq4 * 4]);
            cpa16(wbase + (row * GST + sq4 * 4) * 4,
                  &W[(size_t)(c0 + row) * 512 + kk + sq4 * 4]);
        }
        CPA_COMMIT();
    };

    float acc[2][8][4];
#pragma unroll
    for (int mf = 0; mf < 2; mf++)
#pragma unroll
        for (int nt = 0; nt < 8; nt++)
#pragma unroll
            for (int e = 0; e < 4; e++) acc[mf][nt][e] = 0.f;

    stage(0, 0);

    for (int kc = 0; kc < 16; kc++) {
        if (kc < 15) {
            stage((kc + 1) * 32, (kc + 1) & 1);
            CPA_WAIT1();
        } else {
            CPA_WAIT0();
        }
        __syncthreads();

        const uint32_t* As = Ab + (kc & 1) * GBUF;
        const uint32_t* Ws = Wb + (kc & 1) * GBUF;
#pragma unroll
        for (int kt = 0; kt < 4; kt++) {
            uint32_t a[2][4];
#pragma unroll
            for (int mf = 0; mf < 2; mf++) {
                const int rr = 32 * wm + 16 * mf;
                a[mf][0] = f2tf(__uint_as_float(As[(rr + g) * GST + 8 * kt + c]));
                a[mf][1] = f2tf(__uint_as_float(As[(rr + g + 8) * GST + 8 * kt + c]));
                a[mf][2] = f2tf(__uint_as_float(As[(rr + g) * GST + 8 * kt + c + 4]));
                a[mf][3] = f2tf(__uint_as_float(As[(rr + g + 8) * GST + 8 * kt + c + 4]));
            }
#pragma unroll
            for (int nt = 0; nt < 8; nt++) {
                uint32_t b0 = f2tf(__uint_as_float(Ws[(64 * wn + 8 * nt + g) * GST + 8 * kt + c]));
                uint32_t b1 = f2tf(__uint_as_float(Ws[(64 * wn + 8 * nt + g) * GST + 8 * kt + c + 4]));
                mma8(acc[0][nt], a[0], b0, b1);
                mma8(acc[1][nt], a[1], b0, b1);
            }
        }
        __syncthreads();
    }

    // ---- epilogue ----
#pragma unroll
    for (int nt = 0; nt < 8; nt++) {
        const int col = c0 + 64 * wn + 8 * nt + 2 * c;
        float2 bb = *(const float2*)&bias[col & 511];
#pragma unroll
        for (int mf = 0; mf < 2; mf++) {
#pragma unroll
            for (int rh = 0; rh < 2; rh++) {
                const int row = r0 + 32 * wm + 16 * mf + g + 8 * rh;
                float2 v = make_float2(acc[mf][nt][2 * rh] + bb.x,
                                       acc[mf][nt][2 * rh + 1] + bb.y);
                if (MODE == 0) {
                    const int i = row >> 3, bq = row & 7;
                    const int cl = col & 511;
                    const int hh = cl >> 6, d = cl & 63;
                    if (which == 0) {
                        // Q: prescale + tf32
                        uint2 t = make_uint2(f2tf(v.x * QS), f2tf(v.y * QS));
                        *(uint2*)&g_Qu[(((size_t)(bq * HH + hh)) * NN + i) * DD + d] = t;
                    } else if (which == 1) {
                        // K packed: lane=(j%8)*4+(d%4), comp=(d%8)/4;  j = i
                        uint32_t* dst = g_Kpk + (size_t)(bq * HH + hh) * 65536;
                        uint32_t w0 = (uint32_t)(((i >> 3) * 8 + (d >> 3)) * 64
                                     + ((i & 7) * 4 + (d & 3)) * 2 + ((d >> 2) & 1));
                        dst[w0]     = f2tf(v.x);
                        dst[w0 + 2] = f2tf(v.y);     // d+1: (d&3)+1 -> +2 words
                    } else {
                        // V packed: lane=(d%8)*4+(j%4), comp=(j%8)/4;  j = i
                        uint32_t* dst = g_Vpk + (size_t)(bq * HH + hh) * 65536;
                        uint32_t w0 = (uint32_t)(((i >> 3) * 8 + (d >> 3)) * 64
                                     + ((d & 7) * 4 + (i & 3)) * 2 + ((i >> 2) & 1));
                        dst[w0]     = f2tf(v.x);
                        dst[w0 + 8] = f2tf(v.y);     // d+1: (d&7)+1 -> +8 words
                    }
                } else {
                    *(float2*)&outp[(size_t)row * 512 + col] = v;
                }
            }
        }
    }
}

// ===========================================================================
extern "C" void kernel_launch(void* const* d_in, const int* in_sizes, int n_in,
                              void* d_out, int out_size)
{
    const float* nodes = (const float*)d_in[0];
    const float* edges = (const float*)d_in[1];
    const float* Wq    = (const float*)d_in[2];
    const float* bq    = (const float*)d_in[3];
    const float* Wk    = (const float*)d_in[4];
    const float* bk    = (const float*)d_in[5];
    const float* Wv    = (const float*)d_in[6];
    const float* bv    = (const float*)d_in[7];
    const float* rel   = (const float*)d_in[8];
    const float* Wo    = (const float*)d_in[9];
    const float* bo    = (const float*)d_in[10];
    float* out = (float*)d_out;

    cudaFuncSetAttribute(attn_mma, cudaFuncAttributeMaxDynamicSharedMemorySize, ATT_BYTES);
    cudaFuncSetAttribute(gemm_mma<0>, cudaFuncAttributeMaxDynamicSharedMemorySize, GEMM_BYTES);
    cudaFuncSetAttribute(gemm_mma<1>, cudaFuncAttributeMaxDynamicSharedMemorySize, GEMM_BYTES);

    // Fused QKV projection: blockIdx.y: [0,4)=Q, [4,8)=K, [8,12)=V
    gemm_mma<0><<<dim3(64, 12), 256, GEMM_BYTES>>>(
        nodes, Wq, Wk, Wv, bq, bk, bv, nullptr);

    attn_mma<<<dim3(NN / 128, BB * HH), 128, ATT_BYTES>>>(edges, rel);

    gemm_mma<1><<<dim3(64, 4), 256, GEMM_BYTES>>>(
        nullptr, Wo, Wo, Wo, bo, bo, bo, out);
}

// round 6
// speedup vs baseline: 4.8692x; 1.0344x over previous
#include <cuda_runtime.h>
#include <cstdint>

#define NN 1024
#define BB 8
#define EE 512
#define HH 8
#define DD 64
#define L2E 1.4426950408889634f
#define QS (L2E * 0.125f)

// Scratch (device globals: allocation-free per harness rules)
__device__ uint32_t g_Apk[8192 * 512];       // nodes, A-frag packed tf32
__device__ uint32_t g_Wpk[4 * 262144];       // Wq,Wk,Wv,Wo  B-frag packed tf32
__device__ uint32_t g_Qu [BB * HH * NN * DD]; // Q tf32, prescaled, [bh][n][d]
__device__ uint32_t g_Kpk[BB * HH * 65536];  // K B-frag packed per (bh, j-tile)
__device__ uint32_t g_Vpk[BB * HH * 65536];  // V B-frag packed per (bh, j-tile)
__device__ uint32_t g_Attu[NN * BB * EE];    // attn out, tf32 bits, [n][b][e]

// ---------------------------------------------------------------------------
// helpers
// ---------------------------------------------------------------------------
__device__ __forceinline__ uint32_t f2tf(float f) {
    uint32_t r;
    asm("cvt.rna.tf32.f32 %0, %1;" : "=r"(r) : "f"(f));
    return r;
}
__device__ __forceinline__ float ex2f(float x) {
    float r;
    asm("ex2.approx.f32 %0, %1;" : "=f"(r) : "f"(x));
    return r;
}
__device__ __forceinline__ void mma8(float* d, const uint32_t* a,
                                     uint32_t b0, uint32_t b1) {
    asm volatile(
        "mma.sync.aligned.m16n8k8.row.col.f32.tf32.tf32.f32 "
        "{%0,%1,%2,%3}, {%4,%5,%6,%7}, {%8,%9}, {%0,%1,%2,%3};"
        : "+f"(d[0]), "+f"(d[1]), "+f"(d[2]), "+f"(d[3])
        : "r"(a[0]), "r"(a[1]), "r"(a[2]), "r"(a[3]), "r"(b0), "r"(b1));
}
__device__ __forceinline__ uint32_t smaddr(const void* p) {
    uint32_t a;
    asm("{ .reg .u64 t; cvta.to.shared.u64 t, %1; cvt.u32.u64 %0, t; }" : "=r"(a) : "l"(p));
    return a;
}
__device__ __forceinline__ void cpa16(uint32_t s, const void* g) {
    asm volatile("cp.async.ca.shared.global [%0], [%1], 16;" :: "r"(s), "l"(g) : "memory");
}
#define CPA_COMMIT() asm volatile("cp.async.commit_group;" ::: "memory")
#define CPA_WAIT0()  asm volatile("cp.async.wait_group 0;" ::: "memory")
#define CPA_WAIT1()  asm volatile("cp.async.wait_group 1;" ::: "memory")

// ===========================================================================
// Pre-pack kernels (run once per launch; ~12 us total)
// ===========================================================================
// nodes [8192][512] fp32 -> g_Apk: tile=(m/16)*64+(k/8), word=tile*128+lane*4+comp
// comp order: (m=g,k=c), (g+8,c), (g,c+4), (g+8,c+4);  lane=g*4+c
__global__ void __launch_bounds__(256) prepack_A(const float* __restrict__ src)
{
    const int t    = blockIdx.x * 256 + threadIdx.x;   // 1,048,576 threads
    const int lane = t & 31;
    const int tile = t >> 5;                           // 0..32767
    const int mt = tile >> 6, kt = tile & 63;
    const int g = lane >> 2, c = lane & 3;
    const float* s = src + (size_t)(mt * 16 + g) * 512 + kt * 8 + c;
    uint4 o;
    o.x = f2tf(s[0]);
    o.y = f2tf(s[8 * 512]);
    o.z = f2tf(s[4]);
    o.w = f2tf(s[8 * 512 + 4]);
    *(uint4*)&g_Apk[(size_t)tile * 128 + lane * 4] = o;
}

// W [512][512] (row=n, col=k) -> g_Wpk[which]: tile=(n/8)*64+(k/8),
// word=tile*64+lane*2+comp; lane=(n%8)*4+(k%4); comps k, k+4
__global__ void __launch_bounds__(256) prepack_W(
    const float* __restrict__ Wq, const float* __restrict__ Wk,
    const float* __restrict__ Wv, const float* __restrict__ Wo)
{
    const int which = blockIdx.y;
    const float* __restrict__ W =
        which == 0 ? Wq : which == 1 ? Wk : which == 2 ? Wv : Wo;
    const int t    = blockIdx.x * 256 + threadIdx.x;   // 131,072 threads
    const int lane = t & 31;
    const int tile = t >> 5;                           // 0..4095
    const int nt = tile >> 6, kt = tile & 63;
    const int g = lane >> 2, c = lane & 3;
    const float* s = W + (size_t)(nt * 8 + g) * 512 + kt * 8 + c;
    uint2 o = make_uint2(f2tf(s[0]), f2tf(s[4]));
    *(uint2*)&g_Wpk[(size_t)which * 262144 + tile * 64 + lane * 2] = o;
}

// ===========================================================================
// QKV GEMM: C = nodes @ W^T + b  (packed tf32 fragments, cp.async dbuf)
// Block 128x128, 256 thr (8 warps 4m x 2n), chunk 32k (4 k-tiles).
// Epilogue -> g_Qu (prescaled tf32) / g_Kpk / g_Vpk (attn packed layouts).
// ===========================================================================
#define QKV_BYTES 65536   // 2 stages x (A 16KB + B 16KB)

__global__ void __launch_bounds__(256) gemm_qkv(
    const float* __restrict__ bq, const float* __restrict__ bk,
    const float* __restrict__ bv)
{
    extern __shared__ uint32_t s[];
    const int tid   = threadIdx.x;
    const int which = blockIdx.y >> 2;
    const int c0t   = (blockIdx.y & 3) * 16;   // n-tile base
    const int r0t   = blockIdx.x * 8;          // m-tile base
    const uint32_t* __restrict__ Wg = g_Wpk + (size_t)which * 262144;
    const float* __restrict__ bias = which == 0 ? bq : which == 1 ? bk : bv;

    const int w = tid >> 5, lane = tid & 31;
    const int g = lane >> 2, c = lane & 3;
    const int wm = w & 3, wn = w >> 2;

    auto stage = [&](int kc, int buf) {
        const uint32_t ab = smaddr(s) + buf * 32768;
        const uint32_t bb = ab + 16384;
#pragma unroll
        for (int u = 0; u < 4; u++) {
            const int ua = u * 256 + tid;              // 0..1023
            const int sa = ua >> 7, oa = ua & 127;     // A: 8 segs x 512 w
            cpa16(ab + ua * 16,
                  g_Apk + ((size_t)(r0t + sa) * 64 + kc * 4) * 128 + oa * 4);
            const int sb = ua >> 6, ob = ua & 63;      // B: 16 segs x 256 w
            cpa16(bb + ua * 16,
                  Wg + ((size_t)(c0t + sb) * 64 + kc * 4) * 64 + ob * 4);
        }
        CPA_COMMIT();
    };

    float acc[2][8][4];
#pragma unroll
    for (int mf = 0; mf < 2; mf++)
#pragma unroll
        for (int nt = 0; nt < 8; nt++)
#pragma unroll
            for (int e = 0; e < 4; e++) acc[mf][nt][e] = 0.f;

    stage(0, 0);

    for (int kc = 0; kc < 16; kc++) {
        if (kc < 15) { stage(kc + 1, (kc + 1) & 1); CPA_WAIT1(); }
        else         { CPA_WAIT0(); }
        __syncthreads();

        const uint32_t* As = s + (kc & 1) * 8192;
        const uint32_t* Bs = As + 4096;
#pragma unroll
        for (int kt = 0; kt < 4; kt++) {
            uint4 a0 = *(const uint4*)&As[((wm * 2 + 0) * 4 + kt) * 128 + lane * 4];
            uint4 a1 = *(const uint4*)&As[((wm * 2 + 1) * 4 + kt) * 128 + lane * 4];
#pragma unroll
            for (int nt = 0; nt < 8; nt++) {
                uint2 bb = *(const uint2*)&Bs[((wn * 8 + nt) * 4 + kt) * 64 + lane * 2];
                mma8(acc[0][nt], (const uint32_t*)&a0, bb.x, bb.y);
                mma8(acc[1][nt], (const uint32_t*)&a1, bb.x, bb.y);
            }
        }
        __syncthreads();
    }

    // ---- epilogue: bias + scatter to attn-ready layouts ----
    const int r0 = r0t * 16, c0 = c0t * 8;
#pragma unroll
    for (int nt = 0; nt < 8; nt++) {
        const int col = c0 + 64 * wn + 8 * nt + 2 * c;
        float2 bb = *(const float2*)&bias[col];
#pragma unroll
        for (int mf = 0; mf < 2; mf++) {
#pragma unroll
            for (int rh = 0; rh < 2; rh++) {
                const int row = r0 + 32 * wm + 16 * mf + g + 8 * rh;
                float2 v = make_float2(acc[mf][nt][2 * rh] + bb.x,
                                       acc[mf][nt][2 * rh + 1] + bb.y);
                const int i = row >> 3, bq2 = row & 7;
                const int hh = col >> 6, d = col & 63;
                if (which == 0) {
                    uint2 t = make_uint2(f2tf(v.x * QS), f2tf(v.y * QS));
                    *(uint2*)&g_Qu[(((size_t)(bq2 * HH + hh)) * NN + i) * DD + d] = t;
                } else if (which == 1) {
                    uint32_t* dst = g_Kpk + (size_t)(bq2 * HH + hh) * 65536;
                    uint32_t w0 = (uint32_t)(((i >> 3) * 8 + (d >> 3)) * 64
                                 + ((i & 7) * 4 + (d & 3)) * 2 + ((d >> 2) & 1));
                    dst[w0]     = f2tf(v.x);
                    dst[w0 + 2] = f2tf(v.y);
                } else {
                    uint32_t* dst = g_Vpk + (size_t)(bq2 * HH + hh) * 65536;
                    uint32_t w0 = (uint32_t)(((i >> 3) * 8 + (d >> 3)) * 64
                                 + ((d & 7) * 4 + (i & 3)) * 2 + ((i >> 2) & 1));
                    dst[w0]     = f2tf(v.x);
                    dst[w0 + 8] = f2tf(v.y);
                }
            }
        }
    }
}

// ===========================================================================
// Attention (as round 5) — only change: output stored as tf32 bits.
// ===========================================================================
#define SP 68
#define ATT_P_OFF 16384
#define ATT_BYTES ((16384 + 128 * SP) * 4)

__global__ void __launch_bounds__(128) attn_mma(
    const float* __restrict__ edges, const float* __restrict__ rel)
{
    extern __shared__ uint32_t sm[];
    uint32_t* Ps = sm + ATT_P_OFF;

    const int tid  = threadIdx.x;
    const int w    = tid >> 5;
    const int lane = tid & 31;
    const int g    = lane >> 2;
    const int c    = lane & 3;
    const int bh   = blockIdx.y, b = bh >> 3, h = bh & 7;
    const int i0   = blockIdx.x * 128;
    const float rbl2e = rel[h] * L2E;

    const uint32_t* Qb = g_Qu + ((size_t)bh * NN + i0 + 32 * w) * DD;
    uint32_t qa[2][8][4];
#pragma unroll
    for (int mf = 0; mf < 2; mf++) {
        const uint32_t* Qm = Qb + 16 * mf * DD;
#pragma unroll
        for (int kt = 0; kt < 8; kt++) {
            qa[mf][kt][0] = Qm[g * 64 + 8 * kt + c];
            qa[mf][kt][1] = Qm[(g + 8) * 64 + 8 * kt + c];
            qa[mf][kt][2] = Qm[g * 64 + 8 * kt + c + 4];
            qa[mf][kt][3] = Qm[(g + 8) * 64 + 8 * kt + c + 4];
        }
    }

    float oacc[2][8][4];
#pragma unroll
    for (int mf = 0; mf < 2; mf++)
#pragma unroll
        for (int nt = 0; nt < 8; nt++)
#pragma unroll
            for (int e = 0; e < 4; e++) oacc[mf][nt][e] = 0.f;
    float l00 = 0.f, l01 = 0.f, l10 = 0.f, l11 = 0.f;

    const uint32_t* Kg = g_Kpk + (size_t)bh * 65536;
    const uint32_t* Vg = g_Vpk + (size_t)bh * 65536;

    auto stageKV = [&](int jt, int s) {
        const uint32_t kb = smaddr(sm) + s * 32768;
        const uint32_t vb = kb + 16384;
        const uint32_t* Kt = Kg + jt * 4096;
        const uint32_t* Vt = Vg + jt * 4096;
#pragma unroll
        for (int u = 0; u < 8; u++) {
            const int ch = u * 128 + tid;
            cpa16(kb + ch * 16, Kt + ch * 4);
            cpa16(vb + ch * 16, Vt + ch * 4);
        }
        CPA_COMMIT();
    };

    stageKV(0, 0);

    for (int jt = 0; jt < 16; jt++) {
        const int j0 = jt * 64;
        CPA_WAIT0();
        __syncthreads();

        if (jt < 15) stageKV(jt + 1, (jt + 1) & 1);

        const uint32_t* Ks = sm + (jt & 1) * 8192;
        const uint32_t* Vs = Ks + 4096;
        const int lw = (g * 4 + c) * 2;

        float sacc[2][8][4];
#pragma unroll
        for (int mf = 0; mf < 2; mf++)
#pragma unroll
            for (int nt = 0; nt < 8; nt++)
#pragma unroll
                for (int e = 0; e < 4; e++) sacc[mf][nt][e] = 0.f;
#pragma unroll
        for (int kt = 0; kt < 8; kt++) {
#pragma unroll
            for (int nt = 0; nt < 8; nt++) {
                uint2 bb = *(const uint2*)&Ks[(nt * 8 + kt) * 64 + lw];
                mma8(sacc[0][nt], qa[0][kt], bb.x, bb.y);
                mma8(sacc[1][nt], qa[1][kt], bb.x, bb.y);
            }
        }

#pragma unroll
        for (int mf = 0; mf < 2; mf++) {
            const int rowb = 32 * w + 16 * mf;
            const float* E0 = edges + (size_t)(i0 + rowb + g) * NN + j0;
            const float* E1 = E0 + 8 * NN;
            float ls0 = 0.f, ls1 = 0.f;
#pragma unroll
            for (int nt = 0; nt < 8; nt++) {
                float2 e0 = *(const float2*)(E0 + 8 * nt + 2 * c);
                float2 e1 = *(const float2*)(E1 + 8 * nt + 2 * c);
                float p00 = ex2f(fmaf(e0.x, rbl2e, sacc[mf][nt][0]));
                float p01 = ex2f(fmaf(e0.y, rbl2e, sacc[mf][nt][1]));
                float p10 = ex2f(fmaf(e1.x, rbl2e, sacc[mf][nt][2]));
                float p11 = ex2f(fmaf(e1.y, rbl2e, sacc[mf][nt][3]));
                ls0 += p00 + p01;
                ls1 += p10 + p11;
                *(uint2*)&Ps[(rowb + g) * SP + 8 * nt + 2 * c] =
                    make_uint2(f2tf(p00), f2tf(p01));
                *(uint2*)&Ps[(rowb + g + 8) * SP + 8 * nt + 2 * c] =
                    make_uint2(f2tf(p10), f2tf(p11));
            }
            if (mf == 0) { l00 += ls0; l01 += ls1; }
            else         { l10 += ls0; l11 += ls1; }
        }
        __syncwarp();

#pragma unroll
        for (int kt = 0; kt < 8; kt++) {
            uint32_t a[2][4];
#pragma unroll
            for (int mf = 0; mf < 2; mf++) {
                const int rowb = 32 * w + 16 * mf;
                a[mf][0] = Ps[(rowb + g) * SP + 8 * kt + c];
                a[mf][1] = Ps[(rowb + g + 8) * SP + 8 * kt + c];
                a[mf][2] = Ps[(rowb + g) * SP + 8 * kt + c + 4];
                a[mf][3] = Ps[(rowb + g + 8) * SP + 8 * kt + c + 4];
            }
#pragma unroll
            for (int nt = 0; nt < 8; nt++) {
                uint2 bb = *(const uint2*)&Vs[(kt * 8 + nt) * 64 + lw];
                mma8(oacc[0][nt], a[0], bb.x, bb.y);
                mma8(oacc[1][nt], a[1], bb.x, bb.y);
            }
        }
    }

    l00 += __shfl_xor_sync(0xFFFFFFFF, l00, 1);
    l00 += __shfl_xor_sync(0xFFFFFFFF, l00, 2);
    l01 += __shfl_xor_sync(0xFFFFFFFF, l01, 1);
    l01 += __shfl_xor_sync(0xFFFFFFFF, l01, 2);
    l10 += __shfl_xor_sync(0xFFFFFFFF, l10, 1);
    l10 += __shfl_xor_sync(0xFFFFFFFF, l10, 2);
    l11 += __shfl_xor_sync(0xFFFFFFFF, l11, 1);
    l11 += __shfl_xor_sync(0xFFFFFFFF, l11, 2);
    const float inv[2][2] = {{1.0f / l00, 1.0f / l01}, {1.0f / l10, 1.0f / l11}};

#pragma unroll
    for (int mf = 0; mf < 2; mf++) {
        const int rowb = i0 + 32 * w + 16 * mf;
        uint32_t* O0 = g_Attu + ((size_t)(rowb + g) * BB + b) * EE + h * DD;
        uint32_t* O1 = O0 + (size_t)8 * BB * EE;
#pragma unroll
        for (int nt = 0; nt < 8; nt++) {
            *(uint2*)(O0 + 8 * nt + 2 * c) = make_uint2(
                f2tf(oacc[mf][nt][0] * inv[mf][0]), f2tf(oacc[mf][nt][1] * inv[mf][0]));
            *(uint2*)(O1 + 8 * nt + 2 * c) = make_uint2(
                f2tf(oacc[mf][nt][2] * inv[mf][1]), f2tf(oacc[mf][nt][3] * inv[mf][1]));
        }
    }
}

// ===========================================================================
// Output GEMM: out = Att @ Wo^T + bo.  A = g_Attu (tf32 bits, row layout),
// B = packed Wo (LDS.64 frags, no cvt).
// ===========================================================================
#define GST 36
#define OUT_BYTES ((2 * 128 * GST + 2 * 4096) * 4)   // 69632

__global__ void __launch_bounds__(256) gemm_out(
    const float* __restrict__ bo, float* __restrict__ outp)
{
    extern __shared__ uint32_t s[];
    uint32_t* Ab = s;                 // 2 x 4608
    uint32_t* Bb = s + 2 * 128 * GST;

    const int tid  = threadIdx.x;
    const int c0   = blockIdx.y * 128, c0t = blockIdx.y * 16;
    const int r0   = blockIdx.x * 128;
    const uint32_t* __restrict__ Wg = g_Wpk + 3 * 262144;

    const int w = tid >> 5, lane = tid & 31;
    const int g = lane >> 2, c = lane & 3;
    const int wm = w & 3, wn = w >> 2;
    const int srow = tid >> 3, sq4 = tid & 7;

    auto stage = [&](int kc, int buf) {
        const uint32_t ab = smaddr(Ab) + buf * (128 * GST * 4);
        const uint32_t bb = smaddr(Bb) + buf * 16384;
#pragma unroll
        for (int u = 0; u < 4; u++) {
            const int row = u * 32 + srow;
            cpa16(ab + (row * GST + sq4 * 4) * 4,
                  g_Attu + (size_t)(r0 + row) * 512 + kc * 32 + sq4 * 4);
            const int ua = u * 256 + tid;
            const int sb = ua >> 6, ob = ua & 63;
            cpa16(bb + ua * 16,
                  Wg + ((size_t)(c0t + sb) * 64 + kc * 4) * 64 + ob * 4);
        }
        CPA_COMMIT();
    };

    float acc[2][8][4];
#pragma unroll
    for (int mf = 0; mf < 2; mf++)
#pragma unroll
        for (int nt = 0; nt < 8; nt++)
#pragma unroll
            for (int e = 0; e < 4; e++) acc[mf][nt][e] = 0.f;

    stage(0, 0);

    for (int kc = 0; kc < 16; kc++) {
        if (kc < 15) { stage(kc + 1, (kc + 1) & 1); CPA_WAIT1(); }
        else         { CPA_WAIT0(); }
        __syncthreads();

        const uint32_t* As = Ab + (kc & 1) * (128 * GST);
        const uint32_t* Bs = Bb + (kc & 1) * 4096;
#pragma unroll
        for (int kt = 0; kt < 4; kt++) {
            uint32_t a[2][4];
#pragma unroll
            for (int mf = 0; mf < 2; mf++) {
                const int rr = 32 * wm + 16 * mf;
                a[mf][0] = As[(rr + g) * GST + 8 * kt + c];
                a[mf][1] = As[(rr + g + 8) * GST + 8 * kt + c];
                a[mf][2] = As[(rr + g) * GST + 8 * kt + c + 4];
                a[mf][3] = As[(rr + g + 8) * GST + 8 * kt + c + 4];
            }
#pragma unroll
            for (int nt = 0; nt < 8; nt++) {
                uint2 bb = *(const uint2*)&Bs[((wn * 8 + nt) * 4 + kt) * 64 + lane * 2];
                mma8(acc[0][nt], a[0], bb.x, bb.y);
                mma8(acc[1][nt], a[1], bb.x, bb.y);
            }
        }
        __syncthreads();
    }

#pragma unroll
    for (int nt = 0; nt < 8; nt++) {
        const int col = c0 + 64 * wn + 8 * nt + 2 * c;
        float2 bb = *(const float2*)&bo[col & 511];
#pragma unroll
        for (int mf = 0; mf < 2; mf++) {
#pragma unroll
            for (int rh = 0; rh < 2; rh++) {
                const int row = r0 + 32 * wm + 16 * mf + g + 8 * rh;
                float2 v = make_float2(acc[mf][nt][2 * rh] + bb.x,
                                       acc[mf][nt][2 * rh + 1] + bb.y);
                *(float2*)&outp[(size_t)row * 512 + col] = v;
            }
        }
    }
}

// ===========================================================================
extern "C" void kernel_launch(void* const* d_in, const int* in_sizes, int n_in,
                              void* d_out, int out_size)
{
    const float* nodes = (const float*)d_in[0];
    const float* edges = (const float*)d_in[1];
    const float* Wq    = (const float*)d_in[2];
    const float* bq    = (const float*)d_in[3];
    const float* Wk    = (const float*)d_in[4];
    const float* bk    = (const float*)d_in[5];
    const float* Wv    = (const float*)d_in[6];
    const float* bv    = (const float*)d_in[7];
    const float* rel   = (const float*)d_in[8];
    const float* Wo    = (const float*)d_in[9];
    const float* bo    = (const float*)d_in[10];
    float* out = (float*)d_out;

    cudaFuncSetAttribute(attn_mma, cudaFuncAttributeMaxDynamicSharedMemorySize, ATT_BYTES);
    cudaFuncSetAttribute(gemm_qkv, cudaFuncAttributeMaxDynamicSharedMemorySize, QKV_BYTES);
    cudaFuncSetAttribute(gemm_out, cudaFuncAttributeMaxDynamicSharedMemorySize, OUT_BYTES);

    prepack_A<<<4096, 256>>>(nodes);
    prepack_W<<<dim3(512, 4), 256>>>(Wq, Wk, Wv, Wo);

    gemm_qkv<<<dim3(64, 12), 256, QKV_BYTES>>>(bq, bk, bv);

    attn_mma<<<dim3(NN / 128, BB * HH), 128, ATT_BYTES>>>(edges, rel);

    gemm_out<<<dim3(64, 4), 256, OUT_BYTES>>>(bo, out);
}